// round 1
// baseline (speedup 1.0000x reference)
#include <cuda_runtime.h>
#include <math.h>

// Problem constants (from reference: bs=2, seq=2048, d_model=512, heads=8, d_k=64)
#define DM     512
#define HEADS  8
#define DK     64
#define MAXTOK 4096   // bs*seq
#define MAXBS  2
#define VCHUNK 16

// ---------------- scratch (device globals; no allocations allowed) -------------
__device__ float g_Q[MAXTOK * DM];
__device__ float g_K[MAXTOK * DM];
__device__ float g_V[MAXTOK * DM];
__device__ float g_ctx[MAXTOK * DM];
__device__ float g_vpart[VCHUNK][MAXBS * DM];
__device__ float g_vsum[MAXBS * DM];

// ---------------- fp32 tiled GEMM with bias: C[M,N] = A[M,K] @ B[K,N] + bias ----
#define BM 128
#define BN 128
#define BK 16
#define TM 8
#define TN 8

__global__ __launch_bounds__(256, 2)
void sgemm_bias(const float* __restrict__ A, const float* __restrict__ B,
                const float* __restrict__ bias, float* __restrict__ C,
                int M, int N, int K)
{
    __shared__ float As[BK][BM];
    __shared__ float Bs[BK][BN];

    const int tid = threadIdx.x;           // 0..255
    const int tx  = tid & 15;              // N dir
    const int ty  = tid >> 4;              // M dir

    const float* Ab = A + (size_t)blockIdx.y * BM * K;
    const float* Bb = B + (size_t)blockIdx.x * BN;

    // load mapping
    const int arow = tid >> 2;             // 0..63
    const int acol = (tid & 3) * 4;        // 0,4,8,12
    const int brow = tid >> 5;             // 0..7
    const int bcol = (tid & 31) * 4;       // 0..124

    float acc[TM][TN];
    #pragma unroll
    for (int i = 0; i < TM; i++)
        #pragma unroll
        for (int j = 0; j < TN; j++) acc[i][j] = 0.f;

    for (int k0 = 0; k0 < K; k0 += BK) {
        #pragma unroll
        for (int r = 0; r < 2; r++) {
            float4 v = *(const float4*)(Ab + (size_t)(arow + 64 * r) * K + k0 + acol);
            As[acol + 0][arow + 64 * r] = v.x;
            As[acol + 1][arow + 64 * r] = v.y;
            As[acol + 2][arow + 64 * r] = v.z;
            As[acol + 3][arow + 64 * r] = v.w;
        }
        #pragma unroll
        for (int r = 0; r < 2; r++) {
            float4 v = *(const float4*)(Bb + (size_t)(k0 + brow + 8 * r) * N + bcol);
            *(float4*)&Bs[brow + 8 * r][bcol] = v;
        }
        __syncthreads();

        #pragma unroll
        for (int kk = 0; kk < BK; kk++) {
            float a[TM], b[TN];
            float4 a0 = *(const float4*)&As[kk][ty * TM];
            float4 a1 = *(const float4*)&As[kk][ty * TM + 4];
            a[0]=a0.x; a[1]=a0.y; a[2]=a0.z; a[3]=a0.w;
            a[4]=a1.x; a[5]=a1.y; a[6]=a1.z; a[7]=a1.w;
            float4 b0 = *(const float4*)&Bs[kk][tx * TN];
            float4 b1 = *(const float4*)&Bs[kk][tx * TN + 4];
            b[0]=b0.x; b[1]=b0.y; b[2]=b0.z; b[3]=b0.w;
            b[4]=b1.x; b[5]=b1.y; b[6]=b1.z; b[7]=b1.w;
            #pragma unroll
            for (int i = 0; i < TM; i++)
                #pragma unroll
                for (int j = 0; j < TN; j++)
                    acc[i][j] += a[i] * b[j];
        }
        __syncthreads();
    }

    // epilogue with bias
    #pragma unroll
    for (int i = 0; i < TM; i++) {
        int row = blockIdx.y * BM + ty * TM + i;
        #pragma unroll
        for (int j = 0; j < TN; j += 4) {
            int col = blockIdx.x * BN + tx * TN + j;
            float4 bv = *(const float4*)(bias + col);
            float4 o;
            o.x = acc[i][j + 0] + bv.x;
            o.y = acc[i][j + 1] + bv.y;
            o.z = acc[i][j + 2] + bv.z;
            o.w = acc[i][j + 3] + bv.w;
            *(float4*)(C + (size_t)row * N + col) = o;
        }
    }
}

// ---------------- V column-sum (per batch, per channel) ------------------------
__global__ void vsum_part(const float* __restrict__ V, int seq)
{
    int b = blockIdx.y, chunk = blockIdx.x, c = threadIdx.x;
    int rows = seq / VCHUNK;
    const float* p = V + ((size_t)b * seq + (size_t)chunk * rows) * DM + c;
    float s = 0.f;
    for (int r = 0; r < rows; r++) s += p[(size_t)r * DM];
    g_vpart[chunk][b * DM + c] = s;
}

__global__ void vsum_final(int bs)
{
    int idx = blockIdx.x * blockDim.x + threadIdx.x;
    if (idx >= bs * DM) return;
    float s = 0.f;
    #pragma unroll
    for (int t = 0; t < VCHUNK; t++) s += g_vpart[t][idx];
    g_vsum[idx] = s;
}

// ---------------- banded attention with closed-form full-row softmax ------------
// C[a,b] = max(0, min(seq-1, min(a,b)+2) - max(0, max(a,b)-2) + 1)  (band |a-b|<=4)
// out_i  = (1/Z) [ sum_band (w_j - w0) * v_j + w0 * Vsum ]
// with m = max(0, max_band s), w0 = exp(-m), Z = sum_band w_j + (seq - nb) * w0
__global__ __launch_bounds__(256)
void attn_kernel(const float* __restrict__ Q, const float* __restrict__ K,
                 const float* __restrict__ V, float* __restrict__ ctx, int seq)
{
    int gwarp = (blockIdx.x * blockDim.x + threadIdx.x) >> 5;
    int lane  = threadIdx.x & 31;

    int i  = gwarp % seq;
    int bh = gwarp / seq;
    int h  = bh % HEADS;
    int b  = bh / HEADS;

    const size_t base = ((size_t)b * seq) * DM + h * DK + 2 * lane;

    float2 qv = *(const float2*)(Q + base + (size_t)i * DM);

    int jlo = i - 4; if (jlo < 0) jlo = 0;
    int jhi = i + 4; if (jhi > seq - 1) jhi = seq - 1;
    int nb = jhi - jlo + 1;

    float s[9];
    float smax = 0.f;   // implicit zeros outside the band participate in the max
    #pragma unroll
    for (int t = 0; t < 9; t++) {
        int j = jlo + t;
        bool valid = (j <= jhi);
        int jc = valid ? j : jhi;
        float2 kv = *(const float2*)(K + base + (size_t)jc * DM);
        float p = qv.x * kv.x + qv.y * kv.y;
        #pragma unroll
        for (int o = 16; o; o >>= 1) p += __shfl_xor_sync(0xffffffffu, p, o);
        int mn = min(i, j), mx = max(i, j);
        int clo = mx - 2; if (clo < 0) clo = 0;
        int chi = mn + 2; if (chi > seq - 1) chi = seq - 1;
        float cc = (float)(chi - clo + 1);
        s[t] = valid ? p * 0.125f * cc : -1e30f;
        smax = fmaxf(smax, s[t]);
    }

    float w0 = expf(-smax);
    float Z  = (float)(seq - nb) * w0;
    float w[9];
    #pragma unroll
    for (int t = 0; t < 9; t++) { w[t] = expf(s[t] - smax); Z += w[t]; }
    float rZ = 1.f / Z;

    float2 acc; acc.x = 0.f; acc.y = 0.f;
    #pragma unroll
    for (int t = 0; t < 9; t++) {
        int j = jlo + t;
        bool valid = (j <= jhi);
        int jc = valid ? j : jhi;
        float2 vv = *(const float2*)(V + base + (size_t)jc * DM);
        float wt = valid ? (w[t] - w0) : 0.f;
        acc.x += wt * vv.x;
        acc.y += wt * vv.y;
    }
    float2 vs = *(const float2*)(g_vsum + b * DM + h * DK + 2 * lane);
    acc.x = (acc.x + w0 * vs.x) * rZ;
    acc.y = (acc.y + w0 * vs.y) * rZ;

    *(float2*)(ctx + base + (size_t)i * DM) = acc;
}

// ---------------- launch --------------------------------------------------------
extern "C" void kernel_launch(void* const* d_in, const int* in_sizes, int n_in,
                              void* d_out, int out_size)
{
    const float* q  = (const float*)d_in[0];
    const float* k  = (const float*)d_in[1];
    const float* v  = (const float*)d_in[2];
    const float* Wq = (const float*)d_in[3];
    const float* bq = (const float*)d_in[4];
    const float* Wk = (const float*)d_in[5];
    const float* bk = (const float*)d_in[6];
    const float* Wv = (const float*)d_in[7];
    const float* bv = (const float*)d_in[8];
    const float* Wo = (const float*)d_in[9];
    const float* bo = (const float*)d_in[10];
    float* out = (float*)d_out;

    const int dm     = in_sizes[4];          // 512
    const int tokens = in_sizes[0] / dm;     // bs*seq = 4096
    const int seq    = 2048;
    const int bs     = tokens / seq;         // 2

    float *pQ, *pK, *pV, *pCtx;
    cudaGetSymbolAddress((void**)&pQ,   g_Q);
    cudaGetSymbolAddress((void**)&pK,   g_K);
    cudaGetSymbolAddress((void**)&pV,   g_V);
    cudaGetSymbolAddress((void**)&pCtx, g_ctx);

    dim3 gg(dm / BN, tokens / BM);
    dim3 gb(256);

    sgemm_bias<<<gg, gb>>>(q, Wq, bq, pQ, tokens, dm, dm);
    sgemm_bias<<<gg, gb>>>(k, Wk, bk, pK, tokens, dm, dm);
    sgemm_bias<<<gg, gb>>>(v, Wv, bv, pV, tokens, dm, dm);

    vsum_part<<<dim3(VCHUNK, bs), DM>>>(pV, seq);
    vsum_final<<<(bs * DM + 255) / 256, 256>>>(bs);

    int warps = bs * HEADS * seq;
    attn_kernel<<<warps / 8, 256>>>(pQ, pK, pV, pCtx, seq);

    sgemm_bias<<<gg, gb>>>(pCtx, Wo, bo, out, tokens, dm, dm);
}

// round 4
// speedup vs baseline: 1.7113x; 1.7113x over previous
#include <cuda_runtime.h>
#include <cuda_bf16.h>
#include <math.h>
#include <stdint.h>

// Problem constants: bs=2, seq=2048, d_model=512, heads=8, d_k=64
#define DM     512
#define HEADS  8
#define DK     64
#define SEQ    2048
#define BS     2
#define TOK    (SEQ*BS)     // 4096
#define VCHUNK 64

// ---------------- scratch (device globals; no allocations allowed) -------------
__device__ float g_Q[TOK * DM];
__device__ float g_K[TOK * DM];
__device__ float g_V[TOK * DM];
__device__ float g_ctx[TOK * DM];
__device__ __nv_bfloat16 g_ahi[TOK * DM];
__device__ __nv_bfloat16 g_alo[TOK * DM];
__device__ __nv_bfloat16 g_wthi[4][DM * DM];   // transposed weights [N,K], hi part
__device__ __nv_bfloat16 g_wtlo[4][DM * DM];   // lo part
__device__ float g_vpart[VCHUNK][BS * DM];
__device__ float g_vsum[BS * DM];

// ================= helpers ======================================================
__device__ __forceinline__ uint32_t smem_u32(const void* p) {
    uint32_t a;
    asm("{ .reg .u64 t; cvta.to.shared.u64 t, %1; cvt.u32.u64 %0, t; }" : "=r"(a) : "l"(p));
    return a;
}
__device__ __forceinline__ uint32_t sw128(uint32_t o) { return o ^ ((o >> 3) & 0x70); }

__device__ __forceinline__ void cp16(uint32_t dst, const void* src) {
    asm volatile("cp.async.cg.shared.global [%0], [%1], 16;" :: "r"(dst), "l"(src));
}
__device__ __forceinline__ void ldsm4(uint32_t* r, uint32_t addr) {
    asm volatile("ldmatrix.sync.aligned.m8n8.x4.shared.b16 {%0,%1,%2,%3}, [%4];"
        : "=r"(r[0]), "=r"(r[1]), "=r"(r[2]), "=r"(r[3]) : "r"(addr));
}
__device__ __forceinline__ void mma16816(float* c, const uint32_t* a, uint32_t b0, uint32_t b1) {
    asm volatile("mma.sync.aligned.m16n8k16.row.col.f32.bf16.bf16.f32 "
        "{%0,%1,%2,%3}, {%4,%5,%6,%7}, {%8,%9}, {%0,%1,%2,%3};"
        : "+f"(c[0]), "+f"(c[1]), "+f"(c[2]), "+f"(c[3])
        : "r"(a[0]), "r"(a[1]), "r"(a[2]), "r"(a[3]), "r"(b0), "r"(b1));
}

// ================= bf16-split mma.sync GEMM ====================================
// C[M=TOK, N=DM] = (Ahi+Alo)[M,K] @ (Bhi+Blo)^T + bias, with B stored [N,K].
// CTA tile 128x128, K chunk 64 (128-byte SW128 rows), 2-stage cp.async pipeline.
// 8 warps, warp tile 64(m) x 32(n). 3 products (hh, hl, lh) share one accumulator.
#define KC      64
#define NKC     (DM / KC)               // 8
#define TILE_B  (128 * 128)             // 16 KB per array per stage
#define STG_B   (4 * TILE_B)            // 64 KB per stage
#define GEMM_SMEM (2 * STG_B)           // 131072

__global__ void __launch_bounds__(256, 1)
gemm_mma(const __nv_bfloat16* __restrict__ Ahi, const __nv_bfloat16* __restrict__ Alo,
         const __nv_bfloat16* __restrict__ Bhi, const __nv_bfloat16* __restrict__ Blo,
         const float* __restrict__ bias, float* __restrict__ C)
{
    extern __shared__ char smem[];
    const uint32_t sb = smem_u32(smem);
    const int tid  = threadIdx.x;
    const int wid  = tid >> 5;
    const int lane = tid & 31;
    const int m0   = blockIdx.y * 128;
    const int n0   = blockIdx.x * 128;

    const __nv_bfloat16* arrs[4] = { Ahi, Alo, Bhi, Blo };

    // cp.async mapping: thread -> row tid/2, four 16B chunks (tid&1)*4 .. +3
    const int lrow = tid >> 1;
    const int lc0  = (tid & 1) * 4;

    auto load_stage = [&](int kc, int s) {
        const uint32_t stg = sb + s * STG_B;
        #pragma unroll
        for (int a = 0; a < 4; a++) {
            const int grow = ((a < 2) ? m0 : n0) + lrow;
            const __nv_bfloat16* src = arrs[a] + (size_t)grow * DM + kc * KC + lc0 * 8;
            const uint32_t abase = stg + a * TILE_B;
            #pragma unroll
            for (int c = 0; c < 4; c++)
                cp16(abase + sw128(lrow * 128 + (lc0 + c) * 16), src + c * 8);
        }
        asm volatile("cp.async.commit_group;" ::: "memory");
    };

    load_stage(0, 0);
    load_stage(1, 1);

    // warp tiling
    const int wm = (wid & 1) * 64;       // m offset within CTA tile
    const int wn = (wid >> 1) * 32;      // n offset
    const int lane8 = lane & 7;
    const int rowp8 = ((lane >> 3) & 1) * 8;  // ldmatrix mat bit0 -> +8 rows
    const int kp1   = (lane >> 4) & 1;        // ldmatrix mat bit1 -> +16B (k+8)

    float acc[4][4][4];
    #pragma unroll
    for (int f = 0; f < 4; f++)
        #pragma unroll
        for (int n = 0; n < 4; n++)
            #pragma unroll
            for (int e = 0; e < 4; e++) acc[f][n][e] = 0.f;

    for (int kc = 0; kc < NKC; kc++) {
        const int s = kc & 1;
        if (kc < NKC - 1) asm volatile("cp.async.wait_group 1;" ::: "memory");
        else              asm volatile("cp.async.wait_group 0;" ::: "memory");
        __syncthreads();

        const uint32_t sAh = sb + s * STG_B + 0 * TILE_B;
        const uint32_t sAl = sb + s * STG_B + 1 * TILE_B;
        const uint32_t sBh = sb + s * STG_B + 2 * TILE_B;
        const uint32_t sBl = sb + s * STG_B + 3 * TILE_B;

        #pragma unroll
        for (int kk = 0; kk < KC / 16; kk++) {
            const int ch = kk * 2 + kp1;
            // B fragments: 2 pairs of n8 frags (n = wn .. wn+31), hi and lo
            uint32_t bh[2][4], bl[2][4];
            #pragma unroll
            for (int p = 0; p < 2; p++) {
                const uint32_t off = sw128((wn + p * 16 + lane8 + rowp8) * 128 + ch * 16);
                ldsm4(bh[p], sBh + off);
                ldsm4(bl[p], sBl + off);
            }
            #pragma unroll
            for (int f = 0; f < 4; f++) {
                const uint32_t off = sw128((wm + f * 16 + lane8 + rowp8) * 128 + ch * 16);
                uint32_t ah[4], al[4];
                ldsm4(ah, sAh + off);
                ldsm4(al, sAl + off);
                #pragma unroll
                for (int p = 0; p < 2; p++) {
                    // n-frag 2p uses regs {0,2}; n-frag 2p+1 uses {1,3}
                    mma16816(acc[f][2 * p + 0], ah, bh[p][0], bh[p][2]);
                    mma16816(acc[f][2 * p + 1], ah, bh[p][1], bh[p][3]);
                    mma16816(acc[f][2 * p + 0], ah, bl[p][0], bl[p][2]);
                    mma16816(acc[f][2 * p + 1], ah, bl[p][1], bl[p][3]);
                    mma16816(acc[f][2 * p + 0], al, bh[p][0], bh[p][2]);
                    mma16816(acc[f][2 * p + 1], al, bh[p][1], bh[p][3]);
                }
            }
        }
        __syncthreads();
        if (kc + 2 < NKC) load_stage(kc + 2, s);
    }

    // epilogue: frag (f,n): c0,c1 -> row lane/4, cols n*8+(lane%4)*2; c2,c3 -> row+8
    const int row0 = m0 + wm + (lane >> 2);
    const int colb = n0 + wn + (lane & 3) * 2;
    #pragma unroll
    for (int f = 0; f < 4; f++) {
        #pragma unroll
        for (int n = 0; n < 4; n++) {
            const int col = colb + n * 8;
            const float2 bv = *(const float2*)(bias + col);
            float2 o0, o1;
            o0.x = acc[f][n][0] + bv.x; o0.y = acc[f][n][1] + bv.y;
            o1.x = acc[f][n][2] + bv.x; o1.y = acc[f][n][3] + bv.y;
            *(float2*)(C + (size_t)(row0 + f * 16 + 0) * DM + col) = o0;
            *(float2*)(C + (size_t)(row0 + f * 16 + 8) * DM + col) = o1;
        }
    }
}

// ================= conversion kernels ==========================================
__global__ void conv_act(const float* __restrict__ x, __nv_bfloat16* __restrict__ hi,
                         __nv_bfloat16* __restrict__ lo)
{
    int i = blockIdx.x * blockDim.x + threadIdx.x;   // over float4s
    float4 v = ((const float4*)x)[i];
    __nv_bfloat16 h[4], l[4];
    float f[4] = { v.x, v.y, v.z, v.w };
    #pragma unroll
    for (int t = 0; t < 4; t++) {
        h[t] = __float2bfloat16_rn(f[t]);
        l[t] = __float2bfloat16_rn(f[t] - __bfloat162float(h[t]));
    }
    ((ushort4*)hi)[i] = make_ushort4(__bfloat16_as_ushort(h[0]), __bfloat16_as_ushort(h[1]),
                                     __bfloat16_as_ushort(h[2]), __bfloat16_as_ushort(h[3]));
    ((ushort4*)lo)[i] = make_ushort4(__bfloat16_as_ushort(l[0]), __bfloat16_as_ushort(l[1]),
                                     __bfloat16_as_ushort(l[2]), __bfloat16_as_ushort(l[3]));
}

// W [K,N] fp32 row-major -> Wt [N,K] bf16 hi/lo (transposed), via shared tile
__global__ void wt_trans(const float* __restrict__ W, __nv_bfloat16* __restrict__ hi,
                         __nv_bfloat16* __restrict__ lo)
{
    __shared__ float t[32][33];
    const int bx = blockIdx.x * 32;   // n
    const int by = blockIdx.y * 32;   // k
    const int x = threadIdx.x, y = threadIdx.y;
    #pragma unroll
    for (int r = y; r < 32; r += 8)
        t[r][x] = W[(size_t)(by + r) * DM + bx + x];
    __syncthreads();
    #pragma unroll
    for (int i = y; i < 32; i += 8) {
        float v = t[x][i];
        __nv_bfloat16 h = __float2bfloat16_rn(v);
        __nv_bfloat16 l = __float2bfloat16_rn(v - __bfloat162float(h));
        size_t o = (size_t)(bx + i) * DM + by + x;
        hi[o] = h;
        lo[o] = l;
    }
}

// ================= V column-sum ================================================
__global__ void vsum_part(const float* __restrict__ V)
{
    int b = blockIdx.y, chunk = blockIdx.x, c = threadIdx.x;
    const int rows = SEQ / VCHUNK;
    const float* p = V + ((size_t)b * SEQ + (size_t)chunk * rows) * DM + c;
    float s = 0.f;
    #pragma unroll 4
    for (int r = 0; r < rows; r++) s += p[(size_t)r * DM];
    g_vpart[chunk][b * DM + c] = s;
}

__global__ void vsum_final()
{
    int idx = blockIdx.x * blockDim.x + threadIdx.x;
    if (idx >= BS * DM) return;
    float s = 0.f;
    #pragma unroll
    for (int t = 0; t < VCHUNK; t++) s += g_vpart[t][idx];
    g_vsum[idx] = s;
}

// ================= banded attention (closed-form full-row softmax) ==============
__global__ __launch_bounds__(256)
void attn_kernel(const float* __restrict__ Q, const float* __restrict__ K,
                 const float* __restrict__ V, float* __restrict__ ctx)
{
    int gwarp = (blockIdx.x * blockDim.x + threadIdx.x) >> 5;
    int lane  = threadIdx.x & 31;

    int i  = gwarp % SEQ;
    int bh = gwarp / SEQ;
    int h  = bh % HEADS;
    int b  = bh / HEADS;

    const size_t base = ((size_t)b * SEQ) * DM + h * DK + 2 * lane;
    float2 qv = *(const float2*)(Q + base + (size_t)i * DM);

    int jlo = i - 4; if (jlo < 0) jlo = 0;
    int jhi = i + 4; if (jhi > SEQ - 1) jhi = SEQ - 1;
    int nb = jhi - jlo + 1;

    float s[9];
    float smax = 0.f;
    #pragma unroll
    for (int t = 0; t < 9; t++) {
        int j = jlo + t;
        bool valid = (j <= jhi);
        int jc = valid ? j : jhi;
        float2 kv = *(const float2*)(K + base + (size_t)jc * DM);
        float p = qv.x * kv.x + qv.y * kv.y;
        #pragma unroll
        for (int o = 16; o; o >>= 1) p += __shfl_xor_sync(0xffffffffu, p, o);
        int mn = min(i, j), mx = max(i, j);
        int clo = mx - 2; if (clo < 0) clo = 0;
        int chi = mn + 2; if (chi > SEQ - 1) chi = SEQ - 1;
        float cc = (float)(chi - clo + 1);
        s[t] = valid ? p * 0.125f * cc : -1e30f;
        smax = fmaxf(smax, s[t]);
    }

    float w0 = expf(-smax);
    float Z  = (float)(SEQ - nb) * w0;
    float w[9];
    #pragma unroll
    for (int t = 0; t < 9; t++) { w[t] = expf(s[t] - smax); Z += w[t]; }
    float rZ = 1.f / Z;

    float2 acc; acc.x = 0.f; acc.y = 0.f;
    #pragma unroll
    for (int t = 0; t < 9; t++) {
        int j = jlo + t;
        bool valid = (j <= jhi);
        int jc = valid ? j : jhi;
        float2 vv = *(const float2*)(V + base + (size_t)jc * DM);
        float wt = valid ? (w[t] - w0) : 0.f;
        acc.x += wt * vv.x;
        acc.y += wt * vv.y;
    }
    float2 vs = *(const float2*)(g_vsum + b * DM + h * DK + 2 * lane);
    acc.x = (acc.x + w0 * vs.x) * rZ;
    acc.y = (acc.y + w0 * vs.y) * rZ;

    *(float2*)(ctx + base + (size_t)i * DM) = acc;
}

// ================= launch =======================================================
extern "C" void kernel_launch(void* const* d_in, const int* in_sizes, int n_in,
                              void* d_out, int out_size)
{
    const float* q  = (const float*)d_in[0];
    const float* k  = (const float*)d_in[1];
    const float* v  = (const float*)d_in[2];
    const float* Wq = (const float*)d_in[3];
    const float* bq = (const float*)d_in[4];
    const float* Wk = (const float*)d_in[5];
    const float* bk = (const float*)d_in[6];
    const float* Wv = (const float*)d_in[7];
    const float* bv = (const float*)d_in[8];
    const float* Wo = (const float*)d_in[9];
    const float* bo = (const float*)d_in[10];
    float* out = (float*)d_out;

    float *pQ, *pK, *pV, *pCtx;
    __nv_bfloat16 *pAhi, *pAlo, *pWhi, *pWlo;
    cudaGetSymbolAddress((void**)&pQ,   g_Q);
    cudaGetSymbolAddress((void**)&pK,   g_K);
    cudaGetSymbolAddress((void**)&pV,   g_V);
    cudaGetSymbolAddress((void**)&pCtx, g_ctx);
    cudaGetSymbolAddress((void**)&pAhi, g_ahi);
    cudaGetSymbolAddress((void**)&pAlo, g_alo);
    cudaGetSymbolAddress((void**)&pWhi, g_wthi);
    cudaGetSymbolAddress((void**)&pWlo, g_wtlo);

    cudaFuncSetAttribute(gemm_mma, cudaFuncAttributeMaxDynamicSharedMemorySize, GEMM_SMEM);

    // weight transpose + bf16 split
    dim3 wtg(DM / 32, DM / 32), wtb(32, 8);
    const float* Ws[4] = { Wq, Wk, Wv, Wo };
    for (int i = 0; i < 4; i++)
        wt_trans<<<wtg, wtb>>>(Ws[i], pWhi + (size_t)i * DM * DM, pWlo + (size_t)i * DM * DM);

    dim3 gg(DM / 128, TOK / 128);   // (4, 32) = 128 CTAs
    const int CVB = 256, CVG = (TOK * DM / 4) / CVB;

    // Q = q@Wq+bq ; K = k@Wk+bk ; V = v@Wv+bv
    conv_act<<<CVG, CVB>>>(q, pAhi, pAlo);
    gemm_mma<<<gg, 256, GEMM_SMEM>>>(pAhi, pAlo, pWhi + 0 * (size_t)DM * DM, pWlo + 0 * (size_t)DM * DM, bq, pQ);
    conv_act<<<CVG, CVB>>>(k, pAhi, pAlo);
    gemm_mma<<<gg, 256, GEMM_SMEM>>>(pAhi, pAlo, pWhi + 1 * (size_t)DM * DM, pWlo + 1 * (size_t)DM * DM, bk, pK);
    conv_act<<<CVG, CVB>>>(v, pAhi, pAlo);
    gemm_mma<<<gg, 256, GEMM_SMEM>>>(pAhi, pAlo, pWhi + 2 * (size_t)DM * DM, pWlo + 2 * (size_t)DM * DM, bv, pV);

    // attention
    vsum_part<<<dim3(VCHUNK, BS), DM>>>(pV);
    vsum_final<<<(BS * DM + 255) / 256, 256>>>();
    int warps = BS * HEADS * SEQ;
    attn_kernel<<<warps / 8, 256>>>(pQ, pK, pV, pCtx);

    // out = ctx@Wo+bo
    conv_act<<<CVG, CVB>>>(pCtx, pAhi, pAlo);
    gemm_mma<<<gg, 256, GEMM_SMEM>>>(pAhi, pAlo, pWhi + 3 * (size_t)DM * DM, pWlo + 3 * (size_t)DM * DM, bo, out);
}